// round 2
// baseline (speedup 1.0000x reference)
#include <cuda_runtime.h>
#include <cstdint>

// Problem constants (shapes are fixed by the dataset)
#define BB   4096          // batch
#define HH   300           // hidden
#define TT   64            // sentence len
#define NG   1200          // 4*HH gate columns
#define KK   600           // 2*HH concat K
#define BM   128           // block tile rows (batch)
#define BN   120           // block tile gate-cols (=> 30 hidden units)
#define KC   40            // K chunk (divides 600)
#define PAD  4             // smem padding -> stride 44

// -------- device scratch (no allocations allowed) --------
__device__ float g_H0[2][BB * HH];
__device__ float g_H1[2][BB * HH];
__device__ float g_C0[BB * HH];
__device__ float g_C1[BB * HH];
__device__ float g_Wp0[NG * KK];
__device__ float g_Wp1[NG * KK];
__device__ float g_bp0[NG];
__device__ float g_bp1[NG];

__device__ __forceinline__ float tf32_round(float x) {
    float y;
    asm("cvt.rna.tf32.f32 %0, %1;" : "=f"(y) : "f"(x));
    return y;
}

__device__ __forceinline__ void mma_tf32(float c[4],
                                         uint32_t a0, uint32_t a1, uint32_t a2, uint32_t a3,
                                         uint32_t b0, uint32_t b1) {
    asm volatile(
        "mma.sync.aligned.m16n8k8.row.col.f32.tf32.tf32.f32 "
        "{%0,%1,%2,%3}, {%4,%5,%6,%7}, {%8,%9}, {%0,%1,%2,%3};"
        : "+f"(c[0]), "+f"(c[1]), "+f"(c[2]), "+f"(c[3])
        : "r"(a0), "r"(a1), "r"(a2), "r"(a3), "r"(b0), "r"(b1));
}

__device__ __forceinline__ float sigmoidf_(float x) {
    return 1.0f / (1.0f + expf(-x));
}

// -------- weight permutation + tf32 pre-round --------
// Wp[m][k], m = 4*j + gate, k in [0,600): k<300 -> W_ih[gate*300+j][k], else W_hh[...][k-300]
// bp[m] = b_ih[gate*300+j] + b_hh[gate*300+j]
__global__ void prep_weights(const float* __restrict__ Wih, const float* __restrict__ Whh,
                             const float* __restrict__ bih, const float* __restrict__ bhh,
                             float* __restrict__ Wp, float* __restrict__ bp) {
    int idx = blockIdx.x * blockDim.x + threadIdx.x;
    if (idx >= NG * KK) return;
    int m = idx / KK;
    int k = idx % KK;
    int j = m >> 2;
    int g = m & 3;
    int srow = g * HH + j;
    float v = (k < HH) ? Wih[srow * HH + k] : Whh[srow * HH + (k - HH)];
    Wp[idx] = tf32_round(v);
    if (k == 0) bp[m] = bih[srow] + bhh[srow];
}

// -------- fused LSTM cell: gates GEMM (tf32 mma) + activation + state update --------
// grid: (10, 32)  block: 256 threads (8 warps, each warp = 16 rows x 120 gate-cols)
__global__ __launch_bounds__(256) void lstm_cell(
    const float* __restrict__ X,     // [BB,HH] input x
    const float* __restrict__ Hin,   // [BB,HH] hidden in
    float* __restrict__ Hout,        // [BB,HH] hidden out
    float* __restrict__ C,           // [BB,HH] cell state (in/out)
    const float* __restrict__ Wp,    // [NG,KK] permuted tf32 weights
    const float* __restrict__ bp,    // [NG]
    float* __restrict__ out,         // null or d_out base
    int t) {
    __shared__ __align__(16) float As[BM][KC + PAD];
    __shared__ __align__(16) float Bs[BN][KC + PAD];

    const int tid  = threadIdx.x;
    const int warp = tid >> 5;
    const int lane = tid & 31;
    const int rowBase = blockIdx.y * BM;
    const int mBase   = blockIdx.x * BN;

    float acc[15][4];
#pragma unroll
    for (int i = 0; i < 15; i++) {
        acc[i][0] = 0.f; acc[i][1] = 0.f; acc[i][2] = 0.f; acc[i][3] = 0.f;
    }

    for (int kc = 0; kc < KK; kc += KC) {
        // stage A (x|h), tf32-rounded.  128 rows x 10 float4 = 1280 vec loads
#pragma unroll
        for (int i = tid; i < BM * (KC / 4); i += 256) {
            int r  = i / (KC / 4);
            int c4 = i % (KC / 4);
            int k  = kc + c4 * 4;
            const float* src = (k < HH) ? &X[(rowBase + r) * HH + k]
                                        : &Hin[(rowBase + r) * HH + (k - HH)];
            float4 v = *(const float4*)src;
            v.x = tf32_round(v.x); v.y = tf32_round(v.y);
            v.z = tf32_round(v.z); v.w = tf32_round(v.w);
            *(float4*)&As[r][c4 * 4] = v;
        }
        // stage B (weights, already tf32). 120 rows x 10 float4
        for (int i = tid; i < BN * (KC / 4); i += 256) {
            int r  = i / (KC / 4);
            int c4 = i % (KC / 4);
            float4 v = *(const float4*)&Wp[(mBase + r) * KK + kc + c4 * 4];
            *(float4*)&Bs[r][c4 * 4] = v;
        }
        __syncthreads();

#pragma unroll
        for (int s = 0; s < KC / 8; s++) {
            const int k0 = s * 8;
            const int ar = warp * 16 + (lane >> 2);
            const int ac = k0 + (lane & 3);
            uint32_t a0 = __float_as_uint(As[ar][ac]);
            uint32_t a1 = __float_as_uint(As[ar + 8][ac]);
            uint32_t a2 = __float_as_uint(As[ar][ac + 4]);
            uint32_t a3 = __float_as_uint(As[ar + 8][ac + 4]);
#pragma unroll
            for (int nt = 0; nt < 15; nt++) {
                const int br = nt * 8 + (lane >> 2);
                uint32_t b0 = __float_as_uint(Bs[br][k0 + (lane & 3)]);
                uint32_t b1 = __float_as_uint(Bs[br][k0 + (lane & 3) + 4]);
                mma_tf32(acc[nt], a0, a1, a2, a3, b0, b1);
            }
        }
        __syncthreads();
    }

    // ---- epilogue: bias, gate exchange via shfl, LSTM update ----
    const int r0 = rowBase + warp * 16 + (lane >> 2);   // also r0+8
#pragma unroll
    for (int nt = 0; nt < 15; nt++) {
        const int mloc = nt * 8 + (lane & 3) * 2;
        const int m    = mBase + mloc;
        const float bias0 = bp[m];
        const float bias1 = bp[m + 1];
        float v0 = acc[nt][0] + bias0;
        float v1 = acc[nt][1] + bias1;
        float v2 = acc[nt][2] + bias0;
        float v3 = acc[nt][3] + bias1;
        // pair lanes (even,odd): even holds (i,f) pre-acts, odd holds (g,o)
        float p0 = __shfl_xor_sync(0xffffffffu, v0, 1);
        float p1 = __shfl_xor_sync(0xffffffffu, v1, 1);
        float p2 = __shfl_xor_sync(0xffffffffu, v2, 1);
        float p3 = __shfl_xor_sync(0xffffffffu, v3, 1);
        if (!(lane & 1)) {
            const int j = m >> 2;     // m % 4 == 0 on even lanes
            // row r0
            {
                float i_ = sigmoidf_(v0);
                float f_ = sigmoidf_(v1);
                float g_ = tanhf(p0);
                float o_ = sigmoidf_(p1);
                float cold = C[r0 * HH + j];
                float cn = f_ * cold + i_ * g_;
                float h  = o_ * tanhf(cn);
                C[r0 * HH + j]    = cn;
                Hout[r0 * HH + j] = h;
                if (out) out[r0 * (TT * HH) + t * HH + j] = h;
            }
            // row r0+8
            {
                float i_ = sigmoidf_(v2);
                float f_ = sigmoidf_(v3);
                float g_ = tanhf(p2);
                float o_ = sigmoidf_(p3);
                int r1 = r0 + 8;
                float cold = C[r1 * HH + j];
                float cn = f_ * cold + i_ * g_;
                float h  = o_ * tanhf(cn);
                C[r1 * HH + j]    = cn;
                Hout[r1 * HH + j] = h;
                if (out) out[r1 * (TT * HH) + t * HH + j] = h;
            }
        }
    }
}

extern "C" void kernel_launch(void* const* d_in, const int* in_sizes, int n_in,
                              void* d_out, int out_size) {
    (void)in_sizes; (void)n_in; (void)out_size;
    const float* z    = (const float*)d_in[0];
    const float* Wih0 = (const float*)d_in[1];
    const float* Whh0 = (const float*)d_in[2];
    const float* bih0 = (const float*)d_in[3];
    const float* bhh0 = (const float*)d_in[4];
    const float* Wih1 = (const float*)d_in[5];
    const float* Whh1 = (const float*)d_in[6];
    const float* bih1 = (const float*)d_in[7];
    const float* bhh1 = (const float*)d_in[8];
    float* out = (float*)d_out;

    float *H0, *H1, *C0, *C1, *Wp0, *Wp1, *bp0, *bp1;
    cudaGetSymbolAddress((void**)&H0,  g_H0);
    cudaGetSymbolAddress((void**)&H1,  g_H1);
    cudaGetSymbolAddress((void**)&C0,  g_C0);
    cudaGetSymbolAddress((void**)&C1,  g_C1);
    cudaGetSymbolAddress((void**)&Wp0, g_Wp0);
    cudaGetSymbolAddress((void**)&Wp1, g_Wp1);
    cudaGetSymbolAddress((void**)&bp0, g_bp0);
    cudaGetSymbolAddress((void**)&bp1, g_bp1);

    const size_t NB = (size_t)BB * HH;
    cudaMemsetAsync(H0, 0, NB * sizeof(float));   // only slice [0] is read at t=0, zero both is fine
    cudaMemsetAsync(H1, 0, NB * sizeof(float));
    cudaMemsetAsync(C0, 0, NB * sizeof(float));
    cudaMemsetAsync(C1, 0, NB * sizeof(float));

    const int prepN = NG * KK;
    prep_weights<<<(prepN + 255) / 256, 256>>>(Wih0, Whh0, bih0, bhh0, Wp0, bp0);
    prep_weights<<<(prepN + 255) / 256, 256>>>(Wih1, Whh1, bih1, bhh1, Wp1, bp1);

    dim3 grid(NG / BN, BB / BM);   // (10, 32)
    for (int t = 0; t < TT; t++) {
        int ri = t & 1;
        int wi = ri ^ 1;
        const float* x0 = (t == 0) ? z : (H1 + (size_t)ri * NB);
        lstm_cell<<<grid, 256>>>(x0, H0 + (size_t)ri * NB, H0 + (size_t)wi * NB,
                                 C0, Wp0, bp0, nullptr, t);
        lstm_cell<<<grid, 256>>>(H0 + (size_t)wi * NB, H1 + (size_t)ri * NB,
                                 H1 + (size_t)wi * NB, C1, Wp1, bp1, out, t);
    }
}

// round 4
// speedup vs baseline: 1.5620x; 1.5620x over previous
#include <cuda_runtime.h>
#include <cstdint>

// Problem constants
#define BB   4096          // batch
#define HH   300           // hidden
#define TT   64            // sentence len
#define NG   1200          // 4*HH real gate columns
#define NGP  1280          // padded gate columns (8 * BN)
#define KK   600           // 2*HH concat K
#define BM   128           // block tile rows (batch)
#define BN   160           // block tile gate-cols
#define KC   40            // K chunk (divides 600, 15 chunks)
#define SAS  44            // smem row stride (floats), conflict-free
#define A_ELEMS (BM * SAS)            // 5632 floats
#define B_ELEMS (BN * SAS)            // 7040 floats
#define STAGE_ELEMS (A_ELEMS + B_ELEMS)  // 12672 floats
#define SMEM_BYTES (2 * STAGE_ELEMS * 4) // 101376 bytes

// -------- device scratch (no allocations allowed) --------
__device__ float g_H0[2][BB * HH];
__device__ float g_H1[2][BB * HH];
__device__ float g_C0[BB * HH];
__device__ float g_C1[BB * HH];
__device__ float g_Wp0[NGP * KK];
__device__ float g_Wp1[NGP * KK];
__device__ float g_bp0[NGP];
__device__ float g_bp1[NGP];

__device__ __forceinline__ float tf32_round(float x) {
    float y;
    asm("cvt.rna.tf32.f32 %0, %1;" : "=f"(y) : "f"(x));
    return y;
}

__device__ __forceinline__ uint32_t tf32_bits(float x) {
    float y;
    asm("cvt.rna.tf32.f32 %0, %1;" : "=f"(y) : "f"(x));
    return __float_as_uint(y);
}

__device__ __forceinline__ void mma_tf32(float c[4],
                                         uint32_t a0, uint32_t a1, uint32_t a2, uint32_t a3,
                                         uint32_t b0, uint32_t b1) {
    asm volatile(
        "mma.sync.aligned.m16n8k8.row.col.f32.tf32.tf32.f32 "
        "{%0,%1,%2,%3}, {%4,%5,%6,%7}, {%8,%9}, {%0,%1,%2,%3};"
        : "+f"(c[0]), "+f"(c[1]), "+f"(c[2]), "+f"(c[3])
        : "r"(a0), "r"(a1), "r"(a2), "r"(a3), "r"(b0), "r"(b1));
}

__device__ __forceinline__ float sigmoidf_(float x) {
    return 1.0f / (1.0f + expf(-x));
}

__device__ __forceinline__ void cpa16(float* dst, const float* src) {
    uint32_t d = (uint32_t)__cvta_generic_to_shared(dst);
    asm volatile("cp.async.cg.shared.global [%0], [%1], 16;\n" :: "r"(d), "l"(src));
}

// -------- weight permutation + tf32 pre-round (padded to NGP) --------
// Wp[m][k], m = 4*j + gate for m < 1200; rows [1200,1280) are zero pad.
__global__ void prep_weights(const float* __restrict__ Wih, const float* __restrict__ Whh,
                             const float* __restrict__ bih, const float* __restrict__ bhh,
                             float* __restrict__ Wp, float* __restrict__ bp) {
    int idx = blockIdx.x * blockDim.x + threadIdx.x;
    if (idx >= NGP * KK) return;
    int m = idx / KK;
    int k = idx % KK;
    if (m < NG) {
        int j = m >> 2;
        int g = m & 3;
        int srow = g * HH + j;
        float v = (k < HH) ? Wih[srow * HH + k] : Whh[srow * HH + (k - HH)];
        Wp[idx] = tf32_round(v);
        if (k == 0) bp[m] = bih[srow] + bhh[srow];
    } else {
        Wp[idx] = 0.0f;
        if (k == 0) bp[m] = 0.0f;
    }
}

// -------- fused LSTM cell, cp.async double-buffered --------
// grid: (NGP/BN=8, BB/BM=32) = 256 CTAs -> one wave at 2 CTAs/SM
// block: 256 threads = 8 warps as 4 (rows) x 2 (cols); warp tile 32 x 80.
__global__ __launch_bounds__(256, 2) void lstm_cell(
    const float* __restrict__ X,     // [BB,HH]
    const float* __restrict__ Hin,   // [BB,HH]
    float* __restrict__ Hout,        // [BB,HH]
    float* __restrict__ C,           // [BB,HH] in/out
    const float* __restrict__ Wp,    // [NGP,KK]
    const float* __restrict__ bp,    // [NGP]
    float* __restrict__ out,         // null or d_out base
    int t) {
    extern __shared__ float smem[];

    const int tid  = threadIdx.x;
    const int warp = tid >> 5;
    const int lane = tid & 31;
    const int wr   = warp >> 1;          // 0..3 (row group of 32)
    const int wc   = warp & 1;           // 0..1 (col group of 80)
    const int rowBase = blockIdx.y * BM;
    const int mBase   = blockIdx.x * BN;

    float acc[2][10][4];
#pragma unroll
    for (int mt = 0; mt < 2; mt++)
#pragma unroll
        for (int nt = 0; nt < 10; nt++) {
            acc[mt][nt][0] = 0.f; acc[mt][nt][1] = 0.f;
            acc[mt][nt][2] = 0.f; acc[mt][nt][3] = 0.f;
        }

    // ---- async load of one K chunk into stage buffer ----
    auto load_chunk = [&](int stage, int kc) {
        float* As = smem + stage * STAGE_ELEMS;
        float* Bs = As + A_ELEMS;
        // A: 128 rows x 10 float4
#pragma unroll 2
        for (int i = tid; i < BM * (KC / 4); i += 256) {
            int r  = i / (KC / 4);
            int c4 = i % (KC / 4);
            int k  = kc + c4 * 4;
            const float* src = (k < HH) ? &X[(rowBase + r) * HH + k]
                                        : &Hin[(rowBase + r) * HH + (k - HH)];
            cpa16(&As[r * SAS + c4 * 4], src);
        }
        // B: 160 rows x 10 float4
#pragma unroll 2
        for (int i = tid; i < BN * (KC / 4); i += 256) {
            int r  = i / (KC / 4);
            int c4 = i % (KC / 4);
            cpa16(&Bs[r * SAS + c4 * 4], &Wp[(mBase + r) * KK + kc + c4 * 4]);
        }
    };

    auto compute_chunk = [&](int stage) {
        const float* As = smem + stage * STAGE_ELEMS;
        const float* Bs = As + A_ELEMS;
#pragma unroll
        for (int s = 0; s < KC / 8; s++) {
            const int k0 = s * 8;
            uint32_t a[2][4];
#pragma unroll
            for (int mt = 0; mt < 2; mt++) {
                const int ar = wr * 32 + mt * 16 + (lane >> 2);
                const int ac = k0 + (lane & 3);
                a[mt][0] = tf32_bits(As[ar * SAS + ac]);
                a[mt][1] = tf32_bits(As[(ar + 8) * SAS + ac]);
                a[mt][2] = tf32_bits(As[ar * SAS + ac + 4]);
                a[mt][3] = tf32_bits(As[(ar + 8) * SAS + ac + 4]);
            }
#pragma unroll
            for (int nt = 0; nt < 10; nt++) {
                const int br = wc * 80 + nt * 8 + (lane >> 2);
                uint32_t b0 = __float_as_uint(Bs[br * SAS + k0 + (lane & 3)]);
                uint32_t b1 = __float_as_uint(Bs[br * SAS + k0 + (lane & 3) + 4]);
                mma_tf32(acc[0][nt], a[0][0], a[0][1], a[0][2], a[0][3], b0, b1);
                mma_tf32(acc[1][nt], a[1][0], a[1][1], a[1][2], a[1][3], b0, b1);
            }
        }
    };

    // ---- pipelined mainloop: 15 chunks, 2 stages ----
    load_chunk(0, 0);
    asm volatile("cp.async.commit_group;\n");
    for (int ch = 0; ch < 15; ch++) {
        if (ch < 14) {
            load_chunk((ch + 1) & 1, (ch + 1) * KC);
            asm volatile("cp.async.commit_group;\n");
            asm volatile("cp.async.wait_group 1;\n");
        } else {
            asm volatile("cp.async.wait_group 0;\n");
        }
        __syncthreads();
        compute_chunk(ch & 1);
        __syncthreads();
    }

    // ---- epilogue: bias, gate exchange via shfl, LSTM update ----
#pragma unroll
    for (int mt = 0; mt < 2; mt++) {
        const int r0 = rowBase + wr * 32 + mt * 16 + (lane >> 2);
#pragma unroll
        for (int nt = 0; nt < 10; nt++) {
            const int m = mBase + wc * 80 + nt * 8 + (lane & 3) * 2;
            const float bias0 = bp[m];
            const float bias1 = bp[m + 1];
            float v0 = acc[mt][nt][0] + bias0;
            float v1 = acc[mt][nt][1] + bias1;
            float v2 = acc[mt][nt][2] + bias0;
            float v3 = acc[mt][nt][3] + bias1;
            // pair lanes: even quad-pos holds (i,f), odd quad-pos holds (g,o)
            float p0 = __shfl_xor_sync(0xffffffffu, v0, 1);
            float p1 = __shfl_xor_sync(0xffffffffu, v1, 1);
            float p2 = __shfl_xor_sync(0xffffffffu, v2, 1);
            float p3 = __shfl_xor_sync(0xffffffffu, v3, 1);
            if (!(lane & 1)) {
                const int j = m >> 2;   // m % 4 == 0 on these lanes
                if (j < HH) {
                    {
                        float i_ = sigmoidf_(v0);
                        float f_ = sigmoidf_(v1);
                        float g_ = tanhf(p0);
                        float o_ = sigmoidf_(p1);
                        float cold = C[r0 * HH + j];
                        float cn = f_ * cold + i_ * g_;
                        float h  = o_ * tanhf(cn);
                        C[r0 * HH + j]    = cn;
                        Hout[r0 * HH + j] = h;
                        if (out) out[(size_t)r0 * (TT * HH) + t * HH + j] = h;
                    }
                    {
                        int r1 = r0 + 8;
                        float i_ = sigmoidf_(v2);
                        float f_ = sigmoidf_(v3);
                        float g_ = tanhf(p2);
                        float o_ = sigmoidf_(p3);
                        float cold = C[r1 * HH + j];
                        float cn = f_ * cold + i_ * g_;
                        float h  = o_ * tanhf(cn);
                        C[r1 * HH + j]    = cn;
                        Hout[r1 * HH + j] = h;
                        if (out) out[(size_t)r1 * (TT * HH) + t * HH + j] = h;
                    }
                }
            }
        }
    }
}

extern "C" void kernel_launch(void* const* d_in, const int* in_sizes, int n_in,
                              void* d_out, int out_size) {
    (void)in_sizes; (void)n_in; (void)out_size;
    const float* z    = (const float*)d_in[0];
    const float* Wih0 = (const float*)d_in[1];
    const float* Whh0 = (const float*)d_in[2];
    const float* bih0 = (const float*)d_in[3];
    const float* bhh0 = (const float*)d_in[4];
    const float* Wih1 = (const float*)d_in[5];
    const float* Whh1 = (const float*)d_in[6];
    const float* bih1 = (const float*)d_in[7];
    const float* bhh1 = (const float*)d_in[8];
    float* out = (float*)d_out;

    float *H0, *H1, *C0, *C1, *Wp0, *Wp1, *bp0, *bp1;
    cudaGetSymbolAddress((void**)&H0,  g_H0);
    cudaGetSymbolAddress((void**)&H1,  g_H1);
    cudaGetSymbolAddress((void**)&C0,  g_C0);
    cudaGetSymbolAddress((void**)&C1,  g_C1);
    cudaGetSymbolAddress((void**)&Wp0, g_Wp0);
    cudaGetSymbolAddress((void**)&Wp1, g_Wp1);
    cudaGetSymbolAddress((void**)&bp0, g_bp0);
    cudaGetSymbolAddress((void**)&bp1, g_bp1);

    cudaFuncSetAttribute(lstm_cell, cudaFuncAttributeMaxDynamicSharedMemorySize, SMEM_BYTES);

    const size_t NB = (size_t)BB * HH;
    cudaMemsetAsync(H0, 0, 2 * NB * sizeof(float));
    cudaMemsetAsync(H1, 0, 2 * NB * sizeof(float));
    cudaMemsetAsync(C0, 0, NB * sizeof(float));
    cudaMemsetAsync(C1, 0, NB * sizeof(float));

    const int prepN = NGP * KK;
    prep_weights<<<(prepN + 255) / 256, 256>>>(Wih0, Whh0, bih0, bhh0, Wp0, bp0);
    prep_weights<<<(prepN + 255) / 256, 256>>>(Wih1, Whh1, bih1, bhh1, Wp1, bp1);

    dim3 grid(NGP / BN, BB / BM);   // (8, 32) = 256 CTAs
    for (int t = 0; t < TT; t++) {
        int ri = t & 1;
        int wi = ri ^ 1;
        const float* x0 = (t == 0) ? z : (H1 + (size_t)ri * NB);
        lstm_cell<<<grid, 256, SMEM_BYTES>>>(x0, H0 + (size_t)ri * NB, H0 + (size_t)wi * NB,
                                             C0, Wp0, bp0, nullptr, t);
        lstm_cell<<<grid, 256, SMEM_BYTES>>>(H0 + (size_t)wi * NB, H1 + (size_t)ri * NB,
                                             H1 + (size_t)wi * NB, C1, Wp1, bp1, out, t);
    }
}

// round 6
// speedup vs baseline: 1.8169x; 1.1632x over previous
#include <cuda_runtime.h>
#include <cstdint>

// Problem constants
#define BB   4096          // batch
#define HH   300           // hidden
#define TT   64            // sentence len
#define NG   1200          // 4*HH real gate columns
#define NGP  1280          // padded gate columns (8 * BN)
#define KK   600           // 2*HH concat K
#define BM   128           // block tile rows (batch)
#define BN   160           // block tile gate-cols
#define KC   40            // K chunk (divides 600, 15 chunks)
#define SAS  44            // smem row stride (floats): r*44 mod 32 banks -> conflict-free LDSM
#define A_ELEMS (BM * SAS)               // 5632 floats
#define B_ELEMS (BN * SAS)               // 7040 floats
#define STAGE_ELEMS (A_ELEMS + B_ELEMS)  // 12672 floats
#define STAGE_BYTES (STAGE_ELEMS * 4)    // 50688
#define SMEM_BYTES (2 * STAGE_BYTES)     // 101376

// -------- device scratch (no allocations allowed) --------
__device__ __align__(16) float g_Z[BB * HH];
__device__ __align__(16) float g_H0[2][BB * HH];
__device__ __align__(16) float g_H1[2][BB * HH];
__device__ __align__(16) float g_C0[BB * HH];
__device__ __align__(16) float g_C1[BB * HH];
__device__ __align__(16) float g_Wp0[NGP * KK];
__device__ __align__(16) float g_Wp1[NGP * KK];
__device__ __align__(16) float g_bp0[NGP];
__device__ __align__(16) float g_bp1[NGP];

__device__ __forceinline__ float tf32_round(float x) {
    float y;
    asm("cvt.rna.tf32.f32 %0, %1;" : "=f"(y) : "f"(x));
    return y;
}

__device__ __forceinline__ void mma_tf32(float c[4],
                                         uint32_t a0, uint32_t a1, uint32_t a2, uint32_t a3,
                                         uint32_t b0, uint32_t b1) {
    asm volatile(
        "mma.sync.aligned.m16n8k8.row.col.f32.tf32.tf32.f32 "
        "{%0,%1,%2,%3}, {%4,%5,%6,%7}, {%8,%9}, {%0,%1,%2,%3};"
        : "+f"(c[0]), "+f"(c[1]), "+f"(c[2]), "+f"(c[3])
        : "r"(a0), "r"(a1), "r"(a2), "r"(a3), "r"(b0), "r"(b1));
}

// ldmatrix x4: 4 8x8 b16 matrices; for tf32 use non-transposed (each 32b elem = 2 b16 cols)
#define LDSM4(r, addr)                                                      \
    asm volatile("ldmatrix.sync.aligned.m8n8.x4.shared.b16 {%0,%1,%2,%3}, [%4];" \
                 : "=r"((r)[0]), "=r"((r)[1]), "=r"((r)[2]), "=r"((r)[3])   \
                 : "r"(addr))

__device__ __forceinline__ float sigmoidf_(float x) {
    return __fdividef(1.0f, 1.0f + __expf(-x));
}
__device__ __forceinline__ float ftanh(float x) {
    float e = __expf(-2.0f * x);
    return __fdividef(1.0f - e, 1.0f + e);
}

__device__ __forceinline__ void cpa16(uint32_t dst, const float* src) {
    asm volatile("cp.async.cg.shared.global [%0], [%1], 16;\n" :: "r"(dst), "l"(src));
}

// -------- prep: weight permutation + tf32 pre-round (rows padded to NGP) --------
__global__ void prep_weights(const float* __restrict__ Wih, const float* __restrict__ Whh,
                             const float* __restrict__ bih, const float* __restrict__ bhh,
                             float* __restrict__ Wp, float* __restrict__ bp) {
    int idx = blockIdx.x * blockDim.x + threadIdx.x;
    if (idx >= NGP * KK) return;
    int m = idx / KK;
    int k = idx % KK;
    if (m < NG) {
        int j = m >> 2;
        int g = m & 3;
        int srow = g * HH + j;
        float v = (k < HH) ? Wih[srow * HH + k] : Whh[srow * HH + (k - HH)];
        Wp[idx] = tf32_round(v);
        if (k == 0) bp[m] = bih[srow] + bhh[srow];
    } else {
        Wp[idx] = 0.0f;
        if (k == 0) bp[m] = 0.0f;
    }
}

__global__ void prep_z(const float* __restrict__ z, float* __restrict__ Z) {
    int idx = blockIdx.x * blockDim.x + threadIdx.x;
    if (idx < BB * HH) Z[idx] = tf32_round(z[idx]);
}

// -------- fused LSTM cell: cp.async double-buffer + ldmatrix + mma.sync tf32 --------
// grid (8, 32) = 256 CTAs (one wave @ 2 CTA/SM), 256 threads = 8 warps (4 row x 2 col),
// warp tile 32 rows x 80 gate-cols.
__global__ __launch_bounds__(256, 2) void lstm_cell(
    const float* __restrict__ X,     // [BB,HH] tf32-pre-rounded
    const float* __restrict__ Hin,   // [BB,HH] tf32-pre-rounded
    float* __restrict__ Hout,        // [BB,HH] written tf32-rounded
    float* __restrict__ C,           // [BB,HH] fp32 in/out
    const float* __restrict__ Wp,    // [NGP,KK] tf32
    const float* __restrict__ bp,    // [NGP]
    float* __restrict__ out,         // null or d_out base
    int t) {
    extern __shared__ __align__(16) float smem[];
    uint32_t smemU;
    asm("{ .reg .u64 tmp; cvta.to.shared.u64 tmp, %1; cvt.u32.u64 %0, tmp; }"
        : "=r"(smemU) : "l"(smem));

    const int tid  = threadIdx.x;
    const int warp = tid >> 5;
    const int lane = tid & 31;
    const int wr   = warp >> 1;          // 0..3 row group of 32
    const int wc   = warp & 1;           // 0..1 col group of 80
    const int rowBase = blockIdx.y * BM;
    const int mBase   = blockIdx.x * BN;

    float acc[2][10][4];
#pragma unroll
    for (int mt = 0; mt < 2; mt++)
#pragma unroll
        for (int nt = 0; nt < 10; nt++) {
            acc[mt][nt][0] = 0.f; acc[mt][nt][1] = 0.f;
            acc[mt][nt][2] = 0.f; acc[mt][nt][3] = 0.f;
        }

    // LDSM lane address bases (within stage 0)
    // A x4: lanes 0-7 rows 0-7 @k0, 8-15 rows 8-15 @k0, 16-23 rows 0-7 @k0+4, 24-31 rows 8-15 @k0+4
    const uint32_t aFragBase =
        smemU + (uint32_t)(((wr * 32 + (lane & 15)) * SAS + ((lane >> 4) << 2)) * 4);
    // B x4 (2 n-tiles): lanes 0-7 n0-7 @k0, 8-15 n0-7 @k0+4, 16-23 n8-15 @k0, 24-31 n8-15 @k0+4
    const uint32_t bFragBase =
        smemU + (uint32_t)((A_ELEMS +
                            (wc * 80 + (lane & 7) + ((lane >> 4) << 3)) * SAS +
                            (((lane >> 3) & 1) << 2)) * 4);

    // ---- async load of one K chunk into stage buffer ----
    auto load_chunk = [&](int stage, int kc) {
        const uint32_t a_s = smemU + stage * STAGE_BYTES;
        const uint32_t b_s = a_s + A_ELEMS * 4;
        // A: 128 rows x 10 float4   (16B granules never straddle the k=300 boundary)
#pragma unroll 2
        for (int i = tid; i < BM * (KC / 4); i += 256) {
            int r  = i / (KC / 4);
            int c4 = i % (KC / 4);
            int k  = kc + c4 * 4;
            const float* src = (k < HH) ? &X[(size_t)(rowBase + r) * HH + k]
                                        : &Hin[(size_t)(rowBase + r) * HH + (k - HH)];
            cpa16(a_s + (uint32_t)((r * SAS + c4 * 4) * 4), src);
        }
        // B: 160 rows x 10 float4
#pragma unroll 2
        for (int i = tid; i < BN * (KC / 4); i += 256) {
            int r  = i / (KC / 4);
            int c4 = i % (KC / 4);
            cpa16(b_s + (uint32_t)((r * SAS + c4 * 4) * 4),
                  &Wp[(size_t)(mBase + r) * KK + kc + c4 * 4]);
        }
    };

    auto compute_chunk = [&](int stage) {
        const uint32_t aS = aFragBase + stage * STAGE_BYTES;
        const uint32_t bS = bFragBase + stage * STAGE_BYTES;
#pragma unroll
        for (int s = 0; s < KC / 8; s++) {
            const uint32_t koff = (uint32_t)(s * 32);   // 8 floats
            uint32_t a0[4], a1[4];
            LDSM4(a0, aS + koff);
            LDSM4(a1, aS + (uint32_t)(16 * SAS * 4) + koff);
#pragma unroll
            for (int np = 0; np < 5; np++) {
                uint32_t b[4];
                LDSM4(b, bS + (uint32_t)(np * 16 * SAS * 4) + koff);
                mma_tf32(acc[0][2 * np],     a0[0], a0[1], a0[2], a0[3], b[0], b[1]);
                mma_tf32(acc[1][2 * np],     a1[0], a1[1], a1[2], a1[3], b[0], b[1]);
                mma_tf32(acc[0][2 * np + 1], a0[0], a0[1], a0[2], a0[3], b[2], b[3]);
                mma_tf32(acc[1][2 * np + 1], a1[0], a1[1], a1[2], a1[3], b[2], b[3]);
            }
        }
    };

    // ---- pipelined mainloop: 15 chunks, 2 stages ----
    load_chunk(0, 0);
    asm volatile("cp.async.commit_group;\n");
#pragma unroll 1
    for (int ch = 0; ch < 15; ch++) {
        if (ch < 14) {
            load_chunk((ch + 1) & 1, (ch + 1) * KC);
            asm volatile("cp.async.commit_group;\n");
            asm volatile("cp.async.wait_group 1;\n");
        } else {
            asm volatile("cp.async.wait_group 0;\n");
        }
        __syncthreads();
        compute_chunk(ch & 1);
        __syncthreads();
    }

    // ---- epilogue: bias, gate exchange via shfl, LSTM update ----
#pragma unroll
    for (int mt = 0; mt < 2; mt++) {
        const int r0 = rowBase + wr * 32 + mt * 16 + (lane >> 2);
#pragma unroll
        for (int nt = 0; nt < 10; nt++) {
            const int m = mBase + wc * 80 + nt * 8 + (lane & 3) * 2;
            const float bias0 = bp[m];
            const float bias1 = bp[m + 1];
            float v0 = acc[mt][nt][0] + bias0;
            float v1 = acc[mt][nt][1] + bias1;
            float v2 = acc[mt][nt][2] + bias0;
            float v3 = acc[mt][nt][3] + bias1;
            // pair lanes: even quad-pos holds (i,f), odd holds (g,o)
            float p0 = __shfl_xor_sync(0xffffffffu, v0, 1);
            float p1 = __shfl_xor_sync(0xffffffffu, v1, 1);
            float p2 = __shfl_xor_sync(0xffffffffu, v2, 1);
            float p3 = __shfl_xor_sync(0xffffffffu, v3, 1);
            if (!(lane & 1)) {
                const int j = m >> 2;   // m % 4 == 0 on these lanes
                if (j < HH) {
                    {
                        float i_ = sigmoidf_(v0);
                        float f_ = sigmoidf_(v1);
                        float g_ = ftanh(p0);
                        float o_ = sigmoidf_(p1);
                        float cold = C[(size_t)r0 * HH + j];
                        float cn = f_ * cold + i_ * g_;
                        float h  = o_ * ftanh(cn);
                        C[(size_t)r0 * HH + j]    = cn;
                        Hout[(size_t)r0 * HH + j] = tf32_round(h);
                        if (out) out[(size_t)r0 * (TT * HH) + t * HH + j] = h;
                    }
                    {
                        int r1 = r0 + 8;
                        float i_ = sigmoidf_(v2);
                        float f_ = sigmoidf_(v3);
                        float g_ = ftanh(p2);
                        float o_ = sigmoidf_(p3);
                        float cold = C[(size_t)r1 * HH + j];
                        float cn = f_ * cold + i_ * g_;
                        float h  = o_ * ftanh(cn);
                        C[(size_t)r1 * HH + j]    = cn;
                        Hout[(size_t)r1 * HH + j] = tf32_round(h);
                        if (out) out[(size_t)r1 * (TT * HH) + t * HH + j] = h;
                    }
                }
            }
        }
    }
}

extern "C" void kernel_launch(void* const* d_in, const int* in_sizes, int n_in,
                              void* d_out, int out_size) {
    (void)in_sizes; (void)n_in; (void)out_size;
    const float* z    = (const float*)d_in[0];
    const float* Wih0 = (const float*)d_in[1];
    const float* Whh0 = (const float*)d_in[2];
    const float* bih0 = (const float*)d_in[3];
    const float* bhh0 = (const float*)d_in[4];
    const float* Wih1 = (const float*)d_in[5];
    const float* Whh1 = (const float*)d_in[6];
    const float* bih1 = (const float*)d_in[7];
    const float* bhh1 = (const float*)d_in[8];
    float* out = (float*)d_out;

    float *Z, *H0, *H1, *C0, *C1, *Wp0, *Wp1, *bp0, *bp1;
    cudaGetSymbolAddress((void**)&Z,   g_Z);
    cudaGetSymbolAddress((void**)&H0,  g_H0);
    cudaGetSymbolAddress((void**)&H1,  g_H1);
    cudaGetSymbolAddress((void**)&C0,  g_C0);
    cudaGetSymbolAddress((void**)&C1,  g_C1);
    cudaGetSymbolAddress((void**)&Wp0, g_Wp0);
    cudaGetSymbolAddress((void**)&Wp1, g_Wp1);
    cudaGetSymbolAddress((void**)&bp0, g_bp0);
    cudaGetSymbolAddress((void**)&bp1, g_bp1);

    cudaFuncSetAttribute(lstm_cell, cudaFuncAttributeMaxDynamicSharedMemorySize, SMEM_BYTES);

    const size_t NB = (size_t)BB * HH;
    cudaMemsetAsync(H0, 0, 2 * NB * sizeof(float));
    cudaMemsetAsync(H1, 0, 2 * NB * sizeof(float));
    cudaMemsetAsync(C0, 0, NB * sizeof(float));
    cudaMemsetAsync(C1, 0, NB * sizeof(float));

    const int prepN = NGP * KK;
    prep_weights<<<(prepN + 255) / 256, 256>>>(Wih0, Whh0, bih0, bhh0, Wp0, bp0);
    prep_weights<<<(prepN + 255) / 256, 256>>>(Wih1, Whh1, bih1, bhh1, Wp1, bp1);
    prep_z<<<((int)NB + 255) / 256, 256>>>(z, Z);

    dim3 grid(NGP / BN, BB / BM);   // (8, 32) = 256 CTAs
    for (int t = 0; t < TT; t++) {
        int ri = t & 1;
        int wi = ri ^ 1;
        const float* x0 = (t == 0) ? Z : (H1 + (size_t)ri * NB);
        lstm_cell<<<grid, 256, SMEM_BYTES>>>(x0, H0 + (size_t)ri * NB, H0 + (size_t)wi * NB,
                                             C0, Wp0, bp0, nullptr, t);
        lstm_cell<<<grid, 256, SMEM_BYTES>>>(H0 + (size_t)wi * NB, H1 + (size_t)ri * NB,
                                             H1 + (size_t)wi * NB, C1, Wp1, bp1, out, t);
    }
}